// round 1
// baseline (speedup 1.0000x reference)
#include <cuda_runtime.h>

// Problem constants
constexpr int N = 50000;     // nodes
constexpr int E = 800000;    // edges
constexpr int K = 128;       // feature dim (input to every layer)

// Scratch (device globals — no allocation allowed)
__device__ __align__(16) float g_agg[(size_t)N * K];
__device__ __align__(16) float g_h1[(size_t)N * K];
__device__ __align__(16) float g_h2[(size_t)N * K];
__device__ float g_inv[N];
__device__ int   g_deg[N];

__global__ void zero_deg_kernel() {
    int i = blockIdx.x * blockDim.x + threadIdx.x;
    if (i < N) g_deg[i] = 0;
}

__global__ void deg_kernel(const int* __restrict__ dst) {
    int e = blockIdx.x * blockDim.x + threadIdx.x;
    if (e < E) atomicAdd(&g_deg[dst[e]], 1);
}

__global__ void inv_kernel() {
    int i = blockIdx.x * blockDim.x + threadIdx.x;
    if (i < N) g_inv[i] = 1.0f / (float)(g_deg[i] + 1);
}

__global__ void zero_agg_kernel() {
    int i = blockIdx.x * blockDim.x + threadIdx.x;
    float4* p = (float4*)g_agg;
    if (i < (N * K) / 4) p[i] = make_float4(0.f, 0.f, 0.f, 0.f);
}

// One warp per edge: lane l handles float4 chunk l of the 128-float row.
// src/dst loads are warp-uniform (L1 broadcast). Gather from h[src] (L2-resident),
// scatter-add into g_agg[dst] with a single 128-bit atomic per lane.
__global__ void edge_kernel(const float* __restrict__ x,
                            const int* __restrict__ src,
                            const int* __restrict__ dst,
                            int which_in) {
    int gid  = blockIdx.x * blockDim.x + threadIdx.x;
    int e    = gid >> 5;
    int lane = gid & 31;
    if (e >= E) return;
    const float* h = (which_in == 0) ? x : (which_in == 1 ? g_h1 : g_h2);
    int s = src[e];
    int d = dst[e];
    float4 v = __ldg((const float4*)(h + (size_t)s * K) + lane);
    atomicAdd(((float4*)(g_agg + (size_t)d * K)) + lane, v);
}

// out[node][j] = relu( sum_k ((agg[node][k] + h[node][k]) * inv[node]) * W[j][k] )
// BM=64 rows per block, K-tiles of 16, 256 threads.
// Thread map: tr = tid % RT (row group), tc = tid / RT (col group) so that warp
// lanes stride over rows -> conflict-free As reads (pad 17), Ws reads broadcast.
template <int DOUT, int TM>
__global__ void gemm_kernel(const float* __restrict__ xin,
                            const float* __restrict__ W,
                            float* __restrict__ outp,
                            int which_in, int which_out) {
    constexpr int BM = 64, KT = 16, TN = 4;
    constexpr int RT = BM / TM;     // row-thread count
    constexpr int CT = DOUT / TN;   // col-thread count
    static_assert(RT * CT == 256, "thread layout");

    __shared__ float As[BM][KT + 1];
    __shared__ float Ws[DOUT][KT + 1];

    const float* H = (which_in == 0) ? xin : (which_in == 1 ? g_h1 : g_h2);
    float* O = (which_out == 0) ? outp : (which_out == 1 ? g_h1 : g_h2);

    int tid  = threadIdx.x;
    int base = blockIdx.x * BM;
    int tr = tid % RT;
    int tc = tid / RT;

    float acc[TM][TN];
#pragma unroll
    for (int i = 0; i < TM; i++)
#pragma unroll
        for (int j = 0; j < TN; j++) acc[i][j] = 0.f;

    for (int kt = 0; kt < K; kt += KT) {
        // Load A tile: (agg + h) * inv, fused
#pragma unroll
        for (int t = 0; t < (BM * KT) / 256; t++) {
            int l = tid + t * 256;
            int row = l >> 4, col = l & 15;
            int node = base + row;
            float v = 0.f;
            if (node < N) {
                size_t idx = (size_t)node * K + kt + col;
                v = (g_agg[idx] + H[idx]) * g_inv[node];
            }
            As[row][col] = v;
        }
        // Load W tile (W is [DOUT][K] row-major)
#pragma unroll
        for (int t = 0; t < (DOUT * KT) / 256; t++) {
            int l = tid + t * 256;
            int row = l >> 4, col = l & 15;
            Ws[row][col] = W[(size_t)row * K + kt + col];
        }
        __syncthreads();

#pragma unroll
        for (int kk = 0; kk < KT; kk++) {
            float a[TM], w[TN];
#pragma unroll
            for (int i = 0; i < TM; i++) a[i] = As[tr + i * RT][kk];
#pragma unroll
            for (int j = 0; j < TN; j++) w[j] = Ws[tc * TN + j][kk];
#pragma unroll
            for (int i = 0; i < TM; i++)
#pragma unroll
                for (int j = 0; j < TN; j++)
                    acc[i][j] = fmaf(a[i], w[j], acc[i][j]);
        }
        __syncthreads();
    }

#pragma unroll
    for (int i = 0; i < TM; i++) {
        int node = base + tr + i * RT;
        if (node < N) {
#pragma unroll
            for (int j = 0; j < TN; j++) {
                O[(size_t)node * DOUT + tc * TN + j] = fmaxf(acc[i][j], 0.f);
            }
        }
    }
}

extern "C" void kernel_launch(void* const* d_in, const int* in_sizes, int n_in,
                              void* d_out, int out_size) {
    const float* x  = (const float*)d_in[0];
    const int*   ei = (const int*)d_in[1];
    const float* W1 = (const float*)d_in[2];
    const float* W2 = (const float*)d_in[3];
    const float* W3 = (const float*)d_in[4];
    float* out = (float*)d_out;

    const int* src = ei;
    const int* dst = ei + E;

    const int egrid = (E * 32 + 255) / 256;      // 100000 blocks (1 warp / edge)
    const int ggrid = (N + 63) / 64;             // 782 blocks
    const int zgrid = ((N * K) / 4 + 255) / 256; // zero agg (float4)
    const int ngrid = (N + 255) / 256;

    // Degree / inverse (once)
    zero_deg_kernel<<<ngrid, 256>>>();
    deg_kernel<<<(E + 255) / 256, 256>>>(dst);
    inv_kernel<<<ngrid, 256>>>();

    // Layer 1: x -> h1 (relu)
    zero_agg_kernel<<<zgrid, 256>>>();
    edge_kernel<<<egrid, 256>>>(x, src, dst, 0);
    gemm_kernel<128, 8><<<ggrid, 256>>>(x, W1, nullptr, 0, 1);

    // Layer 2: h1 -> h2 (relu)
    zero_agg_kernel<<<zgrid, 256>>>();
    edge_kernel<<<egrid, 256>>>(x, src, dst, 1);
    gemm_kernel<128, 8><<<ggrid, 256>>>(x, W2, nullptr, 1, 2);

    // Layer 3: h2 -> out (relu)
    zero_agg_kernel<<<zgrid, 256>>>();
    edge_kernel<<<egrid, 256>>>(x, src, dst, 2);
    gemm_kernel<64, 4><<<ggrid, 256>>>(x, W3, out, 2, 0);
}

// round 2
// speedup vs baseline: 1.3072x; 1.3072x over previous
#include <cuda_runtime.h>

constexpr int N = 50000;     // nodes
constexpr int E = 800000;    // edges
constexpr int K = 128;       // feature dim

constexpr int SCAN_BLK = 1024;
constexpr int NBLK = (N + SCAN_BLK - 1) / SCAN_BLK;   // 49

// Scratch (device globals — no allocation allowed)
__device__ __align__(16) float g_agg[(size_t)N * K];
__device__ __align__(16) float g_h1[(size_t)N * K];
__device__ __align__(16) float g_h2[(size_t)N * K];
__device__ float g_inv[N];
__device__ int   g_deg[N];
__device__ int   g_rp[N];        // CSR row pointer (exclusive prefix of deg)
__device__ int   g_pos[N];       // scatter cursor
__device__ int   g_csr[E];       // src indices grouped by dst
__device__ int   g_bsum[NBLK];   // scan block sums

// ---------------- degree / CSR build ----------------

__global__ void zero_deg_kernel() {
    int i = blockIdx.x * blockDim.x + threadIdx.x;
    if (i < N) g_deg[i] = 0;
}

__global__ void deg_kernel(const int* __restrict__ dst) {
    int e = blockIdx.x * blockDim.x + threadIdx.x;
    if (e < E) atomicAdd(&g_deg[dst[e]], 1);
}

__global__ void inv_kernel() {
    int i = blockIdx.x * blockDim.x + threadIdx.x;
    if (i < N) g_inv[i] = 1.0f / (float)(g_deg[i] + 1);
}

// two-level exclusive scan of g_deg into g_rp
__global__ void scan_block_kernel() {
    __shared__ int sm[SCAN_BLK];
    int tid = threadIdx.x;
    int i = blockIdx.x * SCAN_BLK + tid;
    int v = (i < N) ? g_deg[i] : 0;
    sm[tid] = v;
    __syncthreads();
#pragma unroll
    for (int ofs = 1; ofs < SCAN_BLK; ofs <<= 1) {
        int t = (tid >= ofs) ? sm[tid - ofs] : 0;
        __syncthreads();
        sm[tid] += t;
        __syncthreads();
    }
    if (i < N) g_rp[i] = sm[tid] - v;          // exclusive within block
    if (tid == SCAN_BLK - 1) g_bsum[blockIdx.x] = sm[SCAN_BLK - 1];
}

__global__ void scan_sums_kernel() {
    if (threadIdx.x == 0) {
        int run = 0;
        for (int b = 0; b < NBLK; b++) {
            int v = g_bsum[b];
            g_bsum[b] = run;
            run += v;
        }
    }
}

__global__ void scan_add_kernel() {
    int i = blockIdx.x * blockDim.x + threadIdx.x;
    if (i < N) {
        int rp = g_rp[i] + g_bsum[i >> 10];
        g_rp[i] = rp;
        g_pos[i] = rp;
    }
}

__global__ void fill_csr_kernel(const int* __restrict__ src,
                                const int* __restrict__ dst) {
    int e = blockIdx.x * blockDim.x + threadIdx.x;
    if (e < E) {
        int slot = atomicAdd(&g_pos[dst[e]], 1);
        g_csr[slot] = src[e];
    }
}

// ---------------- aggregation (warp per node, atomic-free) ----------------
// g_agg[node] = (sum_{s in nbrs(node)} h[s] + h[node]) * inv[node]
__global__ void agg_kernel(const float* __restrict__ h) {
    int gid  = blockIdx.x * blockDim.x + threadIdx.x;
    int node = gid >> 5;
    int lane = gid & 31;
    if (node >= N) return;

    const float4* hp = (const float4*)h;
    int start = g_rp[node];
    int d     = g_deg[node];

    float4 self = __ldg(hp + (size_t)node * 32 + lane);
    float ax = self.x, ay = self.y, az = self.z, aw = self.w;
    float bx = 0.f, by = 0.f, bz = 0.f, bw = 0.f;
    float cx = 0.f, cy = 0.f, cz = 0.f, cw = 0.f;
    float dx = 0.f, dy = 0.f, dz = 0.f, dw = 0.f;

    int j = 0;
    for (; j + 4 <= d; j += 4) {
        int s0 = g_csr[start + j + 0];
        int s1 = g_csr[start + j + 1];
        int s2 = g_csr[start + j + 2];
        int s3 = g_csr[start + j + 3];
        float4 v0 = __ldg(hp + (size_t)s0 * 32 + lane);
        float4 v1 = __ldg(hp + (size_t)s1 * 32 + lane);
        float4 v2 = __ldg(hp + (size_t)s2 * 32 + lane);
        float4 v3 = __ldg(hp + (size_t)s3 * 32 + lane);
        ax += v0.x; ay += v0.y; az += v0.z; aw += v0.w;
        bx += v1.x; by += v1.y; bz += v1.z; bw += v1.w;
        cx += v2.x; cy += v2.y; cz += v2.z; cw += v2.w;
        dx += v3.x; dy += v3.y; dz += v3.z; dw += v3.w;
    }
    for (; j < d; j++) {
        int s = g_csr[start + j];
        float4 v = __ldg(hp + (size_t)s * 32 + lane);
        ax += v.x; ay += v.y; az += v.z; aw += v.w;
    }

    float inv = g_inv[node];
    float4 r;
    r.x = (ax + bx + cx + dx) * inv;
    r.y = (ay + by + cy + dy) * inv;
    r.z = (az + bz + cz + dz) * inv;
    r.w = (aw + bw + cw + dw) * inv;
    ((float4*)g_agg)[(size_t)node * 32 + lane] = r;
}

// ---------------- GEMM: out = act( g_agg @ W^T ) ----------------
// BM=128 rows/block, KT=16, 256 threads, TM=8 x TN=(DOUT/16) per thread.
template <int DOUT, bool RELU>
__global__ void gemm_kernel(const float* __restrict__ Wm,
                            float* __restrict__ O) {
    constexpr int BM = 128, KT = 16, TM = 8;
    constexpr int TN = DOUT / 16;
    constexpr int RT = 16;

    __shared__ float As[BM][KT + 1];
    __shared__ float Ws[DOUT][KT + 1];

    int tid  = threadIdx.x;
    int base = blockIdx.x * BM;
    int tr = tid % RT;
    int tc = tid / RT;

    float acc[TM][TN];
#pragma unroll
    for (int i = 0; i < TM; i++)
#pragma unroll
        for (int j = 0; j < TN; j++) acc[i][j] = 0.f;

    for (int kt = 0; kt < K; kt += KT) {
#pragma unroll
        for (int t = 0; t < (BM * KT) / 256; t++) {
            int l = tid + t * 256;
            int row = l >> 4, col = l & 15;
            int node = base + row;
            As[row][col] = (node < N) ? g_agg[(size_t)node * K + kt + col] : 0.f;
        }
#pragma unroll
        for (int t = 0; t < (DOUT * KT) / 256; t++) {
            int l = tid + t * 256;
            int row = l >> 4, col = l & 15;
            Ws[row][col] = Wm[(size_t)row * K + kt + col];
        }
        __syncthreads();

#pragma unroll
        for (int kk = 0; kk < KT; kk++) {
            float a[TM], w[TN];
#pragma unroll
            for (int i = 0; i < TM; i++) a[i] = As[tr + i * RT][kk];
#pragma unroll
            for (int j = 0; j < TN; j++) w[j] = Ws[tc * TN + j][kk];
#pragma unroll
            for (int i = 0; i < TM; i++)
#pragma unroll
                for (int j = 0; j < TN; j++)
                    acc[i][j] = fmaf(a[i], w[j], acc[i][j]);
        }
        __syncthreads();
    }

#pragma unroll
    for (int i = 0; i < TM; i++) {
        int node = base + tr + i * RT;
        if (node < N) {
#pragma unroll
            for (int j = 0; j < TN; j++) {
                float v = acc[i][j];
                O[(size_t)node * DOUT + tc * TN + j] = RELU ? fmaxf(v, 0.f) : v;
            }
        }
    }
}

extern "C" void kernel_launch(void* const* d_in, const int* in_sizes, int n_in,
                              void* d_out, int out_size) {
    const float* x  = (const float*)d_in[0];
    const int*   ei = (const int*)d_in[1];
    const float* W1 = (const float*)d_in[2];
    const float* W2 = (const float*)d_in[3];
    const float* W3 = (const float*)d_in[4];
    float* out = (float*)d_out;

    const int* src = ei;
    const int* dst = ei + E;

    const int ngrid  = (N + 255) / 256;
    const int egrid  = (E + 255) / 256;
    const int agrid  = (N * 32 + 255) / 256;   // warp per node
    const int ggrid  = (N + 127) / 128;

    float* h1;  cudaGetSymbolAddress((void**)&h1, g_h1);
    float* h2;  cudaGetSymbolAddress((void**)&h2, g_h2);

    // Degree + CSR build (once per launch)
    zero_deg_kernel<<<ngrid, 256>>>();
    deg_kernel<<<egrid, 256>>>(dst);
    inv_kernel<<<ngrid, 256>>>();
    scan_block_kernel<<<NBLK, SCAN_BLK>>>();
    scan_sums_kernel<<<1, 32>>>();
    scan_add_kernel<<<ngrid, 256>>>();
    fill_csr_kernel<<<egrid, 256>>>(src, dst);

    // Layer 1: x -> h1
    agg_kernel<<<agrid, 256>>>(x);
    gemm_kernel<128, true><<<ggrid, 256>>>(W1, h1);

    // Layer 2: h1 -> h2
    agg_kernel<<<agrid, 256>>>(h1);
    gemm_kernel<128, true><<<ggrid, 256>>>(W2, h2);

    // Layer 3: h2 -> out (final relu)
    agg_kernel<<<agrid, 256>>>(h2);
    gemm_kernel<64, true><<<ggrid, 256>>>(W3, out);
}

// round 4
// speedup vs baseline: 2.0805x; 1.5916x over previous
#include <cuda_runtime.h>
#include <cuda_bf16.h>
#include <cstdint>

constexpr int N = 50000;     // nodes
constexpr int E = 800000;    // edges
constexpr int K = 128;       // feature dim

constexpr int SCAN_BLK = 1024;
constexpr int NBLK = (N + SCAN_BLK - 1) / SCAN_BLK;   // 49

// ---------------- device scratch (no allocation allowed) ----------------
__device__ __align__(16) float g_y[(size_t)N * K];    // GEMM output (pre-agg)
__device__ __align__(16) float g_h[(size_t)N * K];    // activations
__device__ float g_inv[N];
__device__ int   g_deg[N];
__device__ int   g_rp[N];
__device__ int   g_pos[N];
__device__ int   g_csr[E];
__device__ int   g_bsum[NBLK];
// weight splits: W1(16384) W2(16384) W3(8192)
__device__ __align__(16) __nv_bfloat16 g_Whi[16384 + 16384 + 8192];
__device__ __align__(16) __nv_bfloat16 g_Wlo[16384 + 16384 + 8192];

// ---------------- helpers ----------------
__device__ __forceinline__ uint32_t smem_u32(const void* p) {
    uint32_t a;
    asm("{ .reg .u64 t; cvta.to.shared.u64 t, %1; cvt.u32.u64 %0, t; }" : "=r"(a) : "l"(p));
    return a;
}

#define LDMX4(r0, r1, r2, r3, addr)                                            \
    asm volatile("ldmatrix.sync.aligned.m8n8.x4.shared.b16 {%0,%1,%2,%3}, [%4];" \
                 : "=r"(r0), "=r"(r1), "=r"(r2), "=r"(r3) : "r"(addr))

#define MMA16816(d, a, b)                                                       \
    asm volatile("mma.sync.aligned.m16n8k16.row.col.f32.bf16.bf16.f32 "          \
                 "{%0,%1,%2,%3}, {%4,%5,%6,%7}, {%8,%9}, {%0,%1,%2,%3};"         \
                 : "+f"((d)[0]), "+f"((d)[1]), "+f"((d)[2]), "+f"((d)[3])        \
                 : "r"((a)[0]), "r"((a)[1]), "r"((a)[2]), "r"((a)[3]),           \
                   "r"((b)[0]), "r"((b)[1]))

// ---------------- degree / CSR build ----------------
__global__ void zero_deg_kernel() {
    int i = blockIdx.x * blockDim.x + threadIdx.x;
    if (i < N) g_deg[i] = 0;
}
__global__ void deg_kernel(const int* __restrict__ dst) {
    int e = blockIdx.x * blockDim.x + threadIdx.x;
    if (e < E) atomicAdd(&g_deg[dst[e]], 1);
}
__global__ void inv_kernel() {
    int i = blockIdx.x * blockDim.x + threadIdx.x;
    if (i < N) g_inv[i] = 1.0f / (float)(g_deg[i] + 1);
}
__global__ void scan_block_kernel() {
    __shared__ int sm[SCAN_BLK];
    int tid = threadIdx.x;
    int i = blockIdx.x * SCAN_BLK + tid;
    int v = (i < N) ? g_deg[i] : 0;
    sm[tid] = v;
    __syncthreads();
#pragma unroll
    for (int ofs = 1; ofs < SCAN_BLK; ofs <<= 1) {
        int t = (tid >= ofs) ? sm[tid - ofs] : 0;
        __syncthreads();
        sm[tid] += t;
        __syncthreads();
    }
    if (i < N) g_rp[i] = sm[tid] - v;
    if (tid == SCAN_BLK - 1) g_bsum[blockIdx.x] = sm[SCAN_BLK - 1];
}
__global__ void scan_sums_kernel() {
    if (threadIdx.x == 0) {
        int run = 0;
        for (int b = 0; b < NBLK; b++) { int v = g_bsum[b]; g_bsum[b] = run; run += v; }
    }
}
__global__ void scan_add_kernel() {
    int i = blockIdx.x * blockDim.x + threadIdx.x;
    if (i < N) {
        int rp = g_rp[i] + g_bsum[i >> 10];
        g_rp[i] = rp;
        g_pos[i] = rp;
    }
}
__global__ void fill_csr_kernel(const int* __restrict__ src, const int* __restrict__ dst) {
    int e = blockIdx.x * blockDim.x + threadIdx.x;
    if (e < E) {
        int slot = atomicAdd(&g_pos[dst[e]], 1);
        g_csr[slot] = src[e];
    }
}

// ---------------- weight split: fp32 -> bf16 hi/lo ----------------
__global__ void wsplit_kernel(const float* __restrict__ W, int n, int ofs) {
    int i = blockIdx.x * blockDim.x + threadIdx.x;
    if (i < n) {
        float v = W[i];
        __nv_bfloat16 hi = __float2bfloat16_rn(v);
        __nv_bfloat16 lo = __float2bfloat16_rn(v - __bfloat162float(hi));
        g_Whi[ofs + i] = hi;
        g_Wlo[ofs + i] = lo;
    }
}

// ---------------- HMMA GEMM: Y[128-row tile] = H @ W^T ----------------
// A split to bf16 hi/lo in smem (pitch 136 bf16 -> conflict-free ldmatrix);
// W preconverted. 3 passes: Ahi*Bhi + Alo*Bhi + Ahi*Blo, fp32 accumulators.
constexpr int PITCH = 136;            // bf16 elements per smem row
constexpr int A_TILE = 128 * PITCH * 2;  // 34816 bytes

template <int DOUT>
__global__ __launch_bounds__(256, 1)
void mma_gemm_kernel(const float* __restrict__ Hin,
                     const __nv_bfloat16* __restrict__ Whi,
                     const __nv_bfloat16* __restrict__ Wlo,
                     float* __restrict__ Y) {
    constexpr int B_TILE = DOUT * PITCH * 2;
    constexpr int OFF_AHI = 0;
    constexpr int OFF_ALO = A_TILE;
    constexpr int OFF_BHI = 2 * A_TILE;
    constexpr int OFF_BLO = 2 * A_TILE + B_TILE;
    constexpr int NT = DOUT / 16;     // n8-tiles per warp (warp covers DOUT/2 cols)
    constexpr int NG = NT / 2;        // ldmatrix x4 groups per warp

    extern __shared__ char smem[];
    uint32_t sb = smem_u32(smem);
    int tid = threadIdx.x;
    int lane = tid & 31;
    int wid = tid >> 5;
    int wm = wid & 3;                 // M group: rows wm*32 .. +32
    int wn = wid >> 2;                // N group: cols wn*(DOUT/2)
    int base = blockIdx.x * 128;

    // ---- prologue: A fp32 -> bf16 hi/lo into smem ----
    for (int p = tid; p < 128 * 64; p += 256) {
        int r = p >> 6;
        int c = (p & 63) * 2;
        int node = base + r;
        float2 v = make_float2(0.f, 0.f);
        if (node < N) v = *(const float2*)(Hin + (size_t)node * K + c);
        __nv_bfloat162 hi2, lo2;
        hi2.x = __float2bfloat16_rn(v.x);
        hi2.y = __float2bfloat16_rn(v.y);
        lo2.x = __float2bfloat16_rn(v.x - __bfloat162float(hi2.x));
        lo2.y = __float2bfloat16_rn(v.y - __bfloat162float(hi2.y));
        int byte = (r * PITCH + c) * 2;
        *(uint32_t*)(smem + OFF_AHI + byte) = *(uint32_t*)&hi2;
        *(uint32_t*)(smem + OFF_ALO + byte) = *(uint32_t*)&lo2;
    }
    // ---- prologue: W (already bf16 hi/lo) into smem ----
    for (int p = tid; p < DOUT * 64; p += 256) {
        int r = p >> 6;
        int c = (p & 63) * 2;
        int byte = (r * PITCH + c) * 2;
        *(uint32_t*)(smem + OFF_BHI + byte) = ((const uint32_t*)Whi)[p];
        *(uint32_t*)(smem + OFF_BLO + byte) = ((const uint32_t*)Wlo)[p];
    }
    __syncthreads();

    // ---- per-lane ldmatrix base addresses ----
    int m = lane >> 3;                // matrix index within x4
    int lr = lane & 7;                // row within matrix
    int rb = wm * 32;
    int nb = wn * (DOUT / 2);

    // A: x4 = {r0-7 k0-7, r8-15 k0-7, r0-7 k8-15, r8-15 k8-15}
    uint32_t aoff0 = (uint32_t)(((rb + lr + (m & 1) * 8) * PITCH + (m >> 1) * 8) * 2);
    uint32_t aoff1 = aoff0 + 16 * PITCH * 2;
    // B: x4 = {n0-7 k0-7, n0-7 k8-15, n8-15 k0-7, n8-15 k8-15}
    uint32_t boff[NG];
#pragma unroll
    for (int g = 0; g < NG; g++)
        boff[g] = (uint32_t)(((nb + 16 * g + lr + (m >> 1) * 8) * PITCH + (m & 1) * 8) * 2);

    float acc[2][NT][4];
#pragma unroll
    for (int mt = 0; mt < 2; mt++)
#pragma unroll
        for (int nt = 0; nt < NT; nt++)
#pragma unroll
            for (int q = 0; q < 4; q++) acc[mt][nt][q] = 0.f;

    // ---- main loop: 8 k16-steps ----
#pragma unroll
    for (int j = 0; j < 8; j++) {
        uint32_t kb = j * 32;   // 16 bf16 = 32 bytes
        uint32_t ahi[2][4], alo[2][4], bhi[NT][2], blo[NT][2];
        LDMX4(ahi[0][0], ahi[0][1], ahi[0][2], ahi[0][3], sb + OFF_AHI + aoff0 + kb);
        LDMX4(ahi[1][0], ahi[1][1], ahi[1][2], ahi[1][3], sb + OFF_AHI + aoff1 + kb);
        LDMX4(alo[0][0], alo[0][1], alo[0][2], alo[0][3], sb + OFF_ALO + aoff0 + kb);
        LDMX4(alo[1][0], alo[1][1], alo[1][2], alo[1][3], sb + OFF_ALO + aoff1 + kb);
#pragma unroll
        for (int g = 0; g < NG; g++) {
            LDMX4(bhi[2 * g][0], bhi[2 * g][1], bhi[2 * g + 1][0], bhi[2 * g + 1][1],
                  sb + OFF_BHI + boff[g] + kb);
            LDMX4(blo[2 * g][0], blo[2 * g][1], blo[2 * g + 1][0], blo[2 * g + 1][1],
                  sb + OFF_BLO + boff[g] + kb);
        }
#pragma unroll
        for (int mt = 0; mt < 2; mt++)
#pragma unroll
            for (int nt = 0; nt < NT; nt++) {
                MMA16816(acc[mt][nt], ahi[mt], bhi[nt]);
                MMA16816(acc[mt][nt], alo[mt], bhi[nt]);
                MMA16816(acc[mt][nt], ahi[mt], blo[nt]);
            }
    }

    // ---- epilogue ----
    int r0 = base + rb + (lane >> 2);
#pragma unroll
    for (int mt = 0; mt < 2; mt++) {
        int row = r0 + 16 * mt;
#pragma unroll
        for (int nt = 0; nt < NT; nt++) {
            int col = nb + 8 * nt + 2 * (lane & 3);
            if (row < N)
                *(float2*)(Y + (size_t)row * DOUT + col) = make_float2(acc[mt][nt][0], acc[mt][nt][1]);
            if (row + 8 < N)
                *(float2*)(Y + (size_t)(row + 8) * DOUT + col) = make_float2(acc[mt][nt][2], acc[mt][nt][3]);
        }
    }
}

// ---------------- aggregation: h = relu(inv*(sum_nbr y + y_self)) ----------------
__global__ void agg128_kernel(const float* __restrict__ y, float* __restrict__ hout) {
    int gid = blockIdx.x * blockDim.x + threadIdx.x;
    int node = gid >> 5;
    int lane = gid & 31;
    if (node >= N) return;
    const float4* yp = (const float4*)y;
    int start = g_rp[node];
    int d = g_deg[node];
    float4 self = __ldg(yp + (size_t)node * 32 + lane);
    float ax = self.x, ay = self.y, az = self.z, aw = self.w;
    float bx = 0, by = 0, bz = 0, bw = 0, cx = 0, cy = 0, cz = 0, cw = 0, dx = 0, dy = 0, dz = 0, dw = 0;
    int j = 0;
    for (; j + 4 <= d; j += 4) {
        int s0 = g_csr[start + j], s1 = g_csr[start + j + 1], s2 = g_csr[start + j + 2], s3 = g_csr[start + j + 3];
        float4 v0 = __ldg(yp + (size_t)s0 * 32 + lane);
        float4 v1 = __ldg(yp + (size_t)s1 * 32 + lane);
        float4 v2 = __ldg(yp + (size_t)s2 * 32 + lane);
        float4 v3 = __ldg(yp + (size_t)s3 * 32 + lane);
        ax += v0.x; ay += v0.y; az += v0.z; aw += v0.w;
        bx += v1.x; by += v1.y; bz += v1.z; bw += v1.w;
        cx += v2.x; cy += v2.y; cz += v2.z; cw += v2.w;
        dx += v3.x; dy += v3.y; dz += v3.z; dw += v3.w;
    }
    for (; j < d; j++) {
        int s = g_csr[start + j];
        float4 v = __ldg(yp + (size_t)s * 32 + lane);
        ax += v.x; ay += v.y; az += v.z; aw += v.w;
    }
    float inv = g_inv[node];
    float4 r;
    r.x = fmaxf((ax + bx + cx + dx) * inv, 0.f);
    r.y = fmaxf((ay + by + cy + dy) * inv, 0.f);
    r.z = fmaxf((az + bz + cz + dz) * inv, 0.f);
    r.w = fmaxf((aw + bw + cw + dw) * inv, 0.f);
    ((float4*)hout)[(size_t)node * 32 + lane] = r;
}

__global__ void agg64_kernel(const float* __restrict__ y, float* __restrict__ hout) {
    int gid = blockIdx.x * blockDim.x + threadIdx.x;
    int node = gid >> 5;
    int lane = gid & 31;
    if (node >= N) return;
    const float2* yp = (const float2*)y;
    int start = g_rp[node];
    int d = g_deg[node];
    float2 self = __ldg(yp + (size_t)node * 32 + lane);
    float ax = self.x, ay = self.y;
    float bx = 0, by = 0, cx = 0, cy = 0, dx = 0, dy = 0;
    int j = 0;
    for (; j + 4 <= d; j += 4) {
        int s0 = g_csr[start + j], s1 = g_csr[start + j + 1], s2 = g_csr[start + j + 2], s3 = g_csr[start + j + 3];
        float2 v0 = __ldg(yp + (size_t)s0 * 32 + lane);
        float2 v1 = __ldg(yp + (size_t)s1 * 32 + lane);
        float2 v2 = __ldg(yp + (size_t)s2 * 32 + lane);
        float2 v3 = __ldg(yp + (size_t)s3 * 32 + lane);
        ax += v0.x; ay += v0.y;
        bx += v1.x; by += v1.y;
        cx += v2.x; cy += v2.y;
        dx += v3.x; dy += v3.y;
    }
    for (; j < d; j++) {
        int s = g_csr[start + j];
        float2 v = __ldg(yp + (size_t)s * 32 + lane);
        ax += v.x; ay += v.y;
    }
    float inv = g_inv[node];
    float2 r;
    r.x = fmaxf((ax + bx + cx + dx) * inv, 0.f);
    r.y = fmaxf((ay + by + cy + dy) * inv, 0.f);
    ((float2*)hout)[(size_t)node * 32 + lane] = r;
}

extern "C" void kernel_launch(void* const* d_in, const int* in_sizes, int n_in,
                              void* d_out, int out_size) {
    const float* x = (const float*)d_in[0];
    const int* ei = (const int*)d_in[1];
    const float* W1 = (const float*)d_in[2];
    const float* W2 = (const float*)d_in[3];
    const float* W3 = (const float*)d_in[4];
    float* out = (float*)d_out;

    const int* src = ei;
    const int* dst = ei + E;

    const int ngrid = (N + 255) / 256;
    const int egrid = (E + 255) / 256;
    const int agrid = (N * 32 + 255) / 256;
    const int ggrid = (N + 127) / 128;   // 391

    float* y;  cudaGetSymbolAddress((void**)&y, g_y);
    float* h;  cudaGetSymbolAddress((void**)&h, g_h);
    __nv_bfloat16* whi; cudaGetSymbolAddress((void**)&whi, g_Whi);
    __nv_bfloat16* wlo; cudaGetSymbolAddress((void**)&wlo, g_Wlo);

    const int SMEM128 = 2 * A_TILE + 2 * (128 * PITCH * 2);  // 139264
    const int SMEM64  = 2 * A_TILE + 2 * (64 * PITCH * 2);   // 104448
    cudaFuncSetAttribute(mma_gemm_kernel<128>, cudaFuncAttributeMaxDynamicSharedMemorySize, SMEM128);
    cudaFuncSetAttribute(mma_gemm_kernel<64>,  cudaFuncAttributeMaxDynamicSharedMemorySize, SMEM64);

    // CSR build
    zero_deg_kernel<<<ngrid, 256>>>();
    deg_kernel<<<egrid, 256>>>(dst);
    inv_kernel<<<ngrid, 256>>>();
    scan_block_kernel<<<NBLK, SCAN_BLK>>>();
    scan_sums_kernel<<<1, 32>>>();
    scan_add_kernel<<<ngrid, 256>>>();
    fill_csr_kernel<<<egrid, 256>>>(src, dst);

    // weight splits
    wsplit_kernel<<<(16384 + 255) / 256, 256>>>(W1, 16384, 0);
    wsplit_kernel<<<(16384 + 255) / 256, 256>>>(W2, 16384, 16384);
    wsplit_kernel<<<(8192 + 255) / 256, 256>>>(W3, 8192, 32768);

    // Layer 1: y = x @ W1^T ; h = relu(agg(y))
    mma_gemm_kernel<128><<<ggrid, 256, SMEM128>>>(x, whi, wlo, y);
    agg128_kernel<<<agrid, 256>>>(y, h);

    // Layer 2
    mma_gemm_kernel<128><<<ggrid, 256, SMEM128>>>(h, whi + 16384, wlo + 16384, y);
    agg128_kernel<<<agrid, 256>>>(y, h);

    // Layer 3 (64-dim): GEMM then aggregate 64-dim rows straight into out
    mma_gemm_kernel<64><<<ggrid, 256, SMEM64>>>(h, whi + 32768, wlo + 32768, y);
    agg64_kernel<<<agrid, 256>>>(y, out);
}

// round 5
// speedup vs baseline: 2.3358x; 1.1227x over previous
#include <cuda_runtime.h>
#include <cuda_bf16.h>
#include <cuda_fp16.h>
#include <cstdint>

constexpr int N = 50000;     // nodes
constexpr int E = 800000;    // edges
constexpr int K = 128;       // feature dim

constexpr int SCAN_BLK = 1024;
constexpr int NBLK = (N + SCAN_BLK - 1) / SCAN_BLK;   // 49

// ---------------- device scratch (no allocation allowed) ----------------
__device__ __align__(16) __half g_yh[(size_t)N * K];  // GEMM output staged fp16
__device__ __align__(16) float g_h[(size_t)N * K];    // activations (fp32)
__device__ float g_inv[N];
__device__ int   g_deg[N];
__device__ int   g_rp[N];
__device__ int   g_pos[N];
__device__ int   g_csr[E];
__device__ int   g_bsum[NBLK];
// weight splits: W1(16384) W2(16384) W3(8192)
__device__ __align__(16) __nv_bfloat16 g_Whi[16384 + 16384 + 8192];
__device__ __align__(16) __nv_bfloat16 g_Wlo[16384 + 16384 + 8192];

// ---------------- helpers ----------------
__device__ __forceinline__ uint32_t smem_u32(const void* p) {
    uint32_t a;
    asm("{ .reg .u64 t; cvta.to.shared.u64 t, %1; cvt.u32.u64 %0, t; }" : "=r"(a) : "l"(p));
    return a;
}

#define LDMX4(r0, r1, r2, r3, addr)                                            \
    asm volatile("ldmatrix.sync.aligned.m8n8.x4.shared.b16 {%0,%1,%2,%3}, [%4];" \
                 : "=r"(r0), "=r"(r1), "=r"(r2), "=r"(r3) : "r"(addr))

#define MMA16816(d, a, b)                                                       \
    asm volatile("mma.sync.aligned.m16n8k16.row.col.f32.bf16.bf16.f32 "          \
                 "{%0,%1,%2,%3}, {%4,%5,%6,%7}, {%8,%9}, {%0,%1,%2,%3};"         \
                 : "+f"((d)[0]), "+f"((d)[1]), "+f"((d)[2]), "+f"((d)[3])        \
                 : "r"((a)[0]), "r"((a)[1]), "r"((a)[2]), "r"((a)[3]),           \
                   "r"((b)[0]), "r"((b)[1]))

// ---------------- degree / CSR build ----------------
__global__ void zero_deg_kernel() {
    int i = blockIdx.x * blockDim.x + threadIdx.x;
    if (i < N) g_deg[i] = 0;
}
__global__ void deg_kernel(const int* __restrict__ dst) {
    int e = blockIdx.x * blockDim.x + threadIdx.x;
    if (e < E) atomicAdd(&g_deg[dst[e]], 1);
}
__global__ void scan_block_kernel() {
    __shared__ int sm[SCAN_BLK];
    int tid = threadIdx.x;
    int i = blockIdx.x * SCAN_BLK + tid;
    int v = (i < N) ? g_deg[i] : 0;
    sm[tid] = v;
    __syncthreads();
#pragma unroll
    for (int ofs = 1; ofs < SCAN_BLK; ofs <<= 1) {
        int t = (tid >= ofs) ? sm[tid - ofs] : 0;
        __syncthreads();
        sm[tid] += t;
        __syncthreads();
    }
    if (i < N) g_rp[i] = sm[tid] - v;
    if (tid == SCAN_BLK - 1) g_bsum[blockIdx.x] = sm[SCAN_BLK - 1];
}
__global__ void scan_sums_kernel() {
    if (threadIdx.x == 0) {
        int run = 0;
        for (int b = 0; b < NBLK; b++) { int v = g_bsum[b]; g_bsum[b] = run; run += v; }
    }
}
__global__ void scan_add_kernel() {   // also computes inv
    int i = blockIdx.x * blockDim.x + threadIdx.x;
    if (i < N) {
        int rp = g_rp[i] + g_bsum[i >> 10];
        g_rp[i] = rp;
        g_pos[i] = rp;
        g_inv[i] = 1.0f / (float)(g_deg[i] + 1);
    }
}
__global__ void fill_csr_kernel(const int* __restrict__ src, const int* __restrict__ dst) {
    int e = blockIdx.x * blockDim.x + threadIdx.x;
    if (e < E) {
        int slot = atomicAdd(&g_pos[dst[e]], 1);
        g_csr[slot] = src[e];
    }
}

// ---------------- weight split: fp32 -> bf16 hi/lo (all three W at once) ----------------
__global__ void wsplit_kernel(const float* __restrict__ W1, const float* __restrict__ W2,
                              const float* __restrict__ W3) {
    int i = blockIdx.x * blockDim.x + threadIdx.x;
    if (i >= 40960) return;
    float v;
    if (i < 16384) v = W1[i];
    else if (i < 32768) v = W2[i - 16384];
    else v = W3[i - 32768];
    __nv_bfloat16 hi = __float2bfloat16_rn(v);
    __nv_bfloat16 lo = __float2bfloat16_rn(v - __bfloat162float(hi));
    g_Whi[i] = hi;
    g_Wlo[i] = lo;
}

// ---------------- HMMA GEMM: Yh[128-row tile] = fp16(H @ W^T) ----------------
constexpr int PITCH = 136;               // bf16 elements per smem row
constexpr int A_TILE = 128 * PITCH * 2;  // 34816 bytes

template <int DOUT>
__global__ __launch_bounds__(256, 1)
void mma_gemm_kernel(const float* __restrict__ Hin,
                     const __nv_bfloat16* __restrict__ Whi,
                     const __nv_bfloat16* __restrict__ Wlo,
                     __half* __restrict__ Yh) {
    constexpr int B_TILE = DOUT * PITCH * 2;
    constexpr int OFF_AHI = 0;
    constexpr int OFF_ALO = A_TILE;
    constexpr int OFF_BHI = 2 * A_TILE;
    constexpr int OFF_BLO = 2 * A_TILE + B_TILE;
    constexpr int NT = DOUT / 16;
    constexpr int NG = NT / 2;

    extern __shared__ char smem[];
    uint32_t sb = smem_u32(smem);
    int tid = threadIdx.x;
    int lane = tid & 31;
    int wid = tid >> 5;
    int wm = wid & 3;
    int wn = wid >> 2;
    int base = blockIdx.x * 128;

    for (int p = tid; p < 128 * 64; p += 256) {
        int r = p >> 6;
        int c = (p & 63) * 2;
        int node = base + r;
        float2 v = make_float2(0.f, 0.f);
        if (node < N) v = *(const float2*)(Hin + (size_t)node * K + c);
        __nv_bfloat162 hi2, lo2;
        hi2.x = __float2bfloat16_rn(v.x);
        hi2.y = __float2bfloat16_rn(v.y);
        lo2.x = __float2bfloat16_rn(v.x - __bfloat162float(hi2.x));
        lo2.y = __float2bfloat16_rn(v.y - __bfloat162float(hi2.y));
        int byte = (r * PITCH + c) * 2;
        *(uint32_t*)(smem + OFF_AHI + byte) = *(uint32_t*)&hi2;
        *(uint32_t*)(smem + OFF_ALO + byte) = *(uint32_t*)&lo2;
    }
    for (int p = tid; p < DOUT * 64; p += 256) {
        int r = p >> 6;
        int c = (p & 63) * 2;
        int byte = (r * PITCH + c) * 2;
        *(uint32_t*)(smem + OFF_BHI + byte) = ((const uint32_t*)Whi)[p];
        *(uint32_t*)(smem + OFF_BLO + byte) = ((const uint32_t*)Wlo)[p];
    }
    __syncthreads();

    int m = lane >> 3;
    int lr = lane & 7;
    int rb = wm * 32;
    int nb = wn * (DOUT / 2);

    uint32_t aoff0 = (uint32_t)(((rb + lr + (m & 1) * 8) * PITCH + (m >> 1) * 8) * 2);
    uint32_t aoff1 = aoff0 + 16 * PITCH * 2;
    uint32_t boff[NG];
#pragma unroll
    for (int g = 0; g < NG; g++)
        boff[g] = (uint32_t)(((nb + 16 * g + lr + (m >> 1) * 8) * PITCH + (m & 1) * 8) * 2);

    float acc[2][NT][4];
#pragma unroll
    for (int mt = 0; mt < 2; mt++)
#pragma unroll
        for (int nt = 0; nt < NT; nt++)
#pragma unroll
            for (int q = 0; q < 4; q++) acc[mt][nt][q] = 0.f;

#pragma unroll
    for (int j = 0; j < 8; j++) {
        uint32_t kb = j * 32;
        uint32_t ahi[2][4], alo[2][4], bhi[NT][2], blo[NT][2];
        LDMX4(ahi[0][0], ahi[0][1], ahi[0][2], ahi[0][3], sb + OFF_AHI + aoff0 + kb);
        LDMX4(ahi[1][0], ahi[1][1], ahi[1][2], ahi[1][3], sb + OFF_AHI + aoff1 + kb);
        LDMX4(alo[0][0], alo[0][1], alo[0][2], alo[0][3], sb + OFF_ALO + aoff0 + kb);
        LDMX4(alo[1][0], alo[1][1], alo[1][2], alo[1][3], sb + OFF_ALO + aoff1 + kb);
#pragma unroll
        for (int g = 0; g < NG; g++) {
            LDMX4(bhi[2 * g][0], bhi[2 * g][1], bhi[2 * g + 1][0], bhi[2 * g + 1][1],
                  sb + OFF_BHI + boff[g] + kb);
            LDMX4(blo[2 * g][0], blo[2 * g][1], blo[2 * g + 1][0], blo[2 * g + 1][1],
                  sb + OFF_BLO + boff[g] + kb);
        }
#pragma unroll
        for (int mt = 0; mt < 2; mt++)
#pragma unroll
            for (int nt = 0; nt < NT; nt++) {
                MMA16816(acc[mt][nt], ahi[mt], bhi[nt]);
                MMA16816(acc[mt][nt], alo[mt], bhi[nt]);
                MMA16816(acc[mt][nt], ahi[mt], blo[nt]);
            }
    }

    // epilogue: fp16 stores
    int r0 = base + rb + (lane >> 2);
#pragma unroll
    for (int mt = 0; mt < 2; mt++) {
        int row = r0 + 16 * mt;
#pragma unroll
        for (int nt = 0; nt < NT; nt++) {
            int col = nb + 8 * nt + 2 * (lane & 3);
            if (row < N) {
                __half2 h = __floats2half2_rn(acc[mt][nt][0], acc[mt][nt][1]);
                *(__half2*)(Yh + (size_t)row * DOUT + col) = h;
            }
            if (row + 8 < N) {
                __half2 h = __floats2half2_rn(acc[mt][nt][2], acc[mt][nt][3]);
                *(__half2*)(Yh + (size_t)(row + 8) * DOUT + col) = h;
            }
        }
    }
}

// ---------------- aggregation (fp16 gather): h = relu(inv*(sum_nbr y + y_self)) ----------------
__device__ __forceinline__ void acc_half4(float& a0, float& a1, float& a2, float& a3, uint2 u) {
    float2 f0 = __half22float2(*(__half2*)&u.x);
    float2 f1 = __half22float2(*(__half2*)&u.y);
    a0 += f0.x; a1 += f0.y; a2 += f1.x; a3 += f1.y;
}

// 128-dim: warp per node, lane handles 4 consecutive halves (8 bytes)
__global__ void agg128_kernel(float* __restrict__ hout) {
    int gid = blockIdx.x * blockDim.x + threadIdx.x;
    int node = gid >> 5;
    int lane = gid & 31;
    if (node >= N) return;
    const uint2* yp = (const uint2*)g_yh;   // 32 uint2 per 128-dim row
    int start = g_rp[node];
    int d = g_deg[node];

    float a0 = 0, a1 = 0, a2 = 0, a3 = 0;
    float b0 = 0, b1 = 0, b2 = 0, b3 = 0;
    float c0 = 0, c1 = 0, c2 = 0, c3 = 0;
    float d0 = 0, d1 = 0, d2 = 0, d3 = 0;

    acc_half4(a0, a1, a2, a3, __ldg(yp + (size_t)node * 32 + lane));  // self

    int j = 0;
    for (; j + 4 <= d; j += 4) {
        int s0 = g_csr[start + j], s1 = g_csr[start + j + 1];
        int s2 = g_csr[start + j + 2], s3 = g_csr[start + j + 3];
        uint2 u0 = __ldg(yp + (size_t)s0 * 32 + lane);
        uint2 u1 = __ldg(yp + (size_t)s1 * 32 + lane);
        uint2 u2 = __ldg(yp + (size_t)s2 * 32 + lane);
        uint2 u3 = __ldg(yp + (size_t)s3 * 32 + lane);
        acc_half4(a0, a1, a2, a3, u0);
        acc_half4(b0, b1, b2, b3, u1);
        acc_half4(c0, c1, c2, c3, u2);
        acc_half4(d0, d1, d2, d3, u3);
    }
    for (; j < d; j++) {
        int s = g_csr[start + j];
        acc_half4(a0, a1, a2, a3, __ldg(yp + (size_t)s * 32 + lane));
    }
    float inv = g_inv[node];
    float4 r;
    r.x = fmaxf((a0 + b0 + c0 + d0) * inv, 0.f);
    r.y = fmaxf((a1 + b1 + c1 + d1) * inv, 0.f);
    r.z = fmaxf((a2 + b2 + c2 + d2) * inv, 0.f);
    r.w = fmaxf((a3 + b3 + c3 + d3) * inv, 0.f);
    ((float4*)hout)[(size_t)node * 32 + lane] = r;
}

// 64-dim: warp per node, lane handles 2 halves (4 bytes); writes fp32 out
__global__ void agg64_kernel(float* __restrict__ hout) {
    int gid = blockIdx.x * blockDim.x + threadIdx.x;
    int node = gid >> 5;
    int lane = gid & 31;
    if (node >= N) return;
    const uint32_t* yp = (const uint32_t*)g_yh;   // 32 half2 per 64-dim row
    int start = g_rp[node];
    int d = g_deg[node];

    float a0 = 0, a1 = 0, b0 = 0, b1 = 0, c0 = 0, c1 = 0, d0 = 0, d1 = 0;
    {
        uint32_t u = __ldg(yp + (size_t)node * 32 + lane);
        float2 f = __half22float2(*(__half2*)&u);
        a0 += f.x; a1 += f.y;
    }
    int j = 0;
    for (; j + 4 <= d; j += 4) {
        int s0 = g_csr[start + j], s1 = g_csr[start + j + 1];
        int s2 = g_csr[start + j + 2], s3 = g_csr[start + j + 3];
        uint32_t u0 = __ldg(yp + (size_t)s0 * 32 + lane);
        uint32_t u1 = __ldg(yp + (size_t)s1 * 32 + lane);
        uint32_t u2 = __ldg(yp + (size_t)s2 * 32 + lane);
        uint32_t u3 = __ldg(yp + (size_t)s3 * 32 + lane);
        float2 f0 = __half22float2(*(__half2*)&u0);
        float2 f1 = __half22float2(*(__half2*)&u1);
        float2 f2 = __half22float2(*(__half2*)&u2);
        float2 f3 = __half22float2(*(__half2*)&u3);
        a0 += f0.x; a1 += f0.y;
        b0 += f1.x; b1 += f1.y;
        c0 += f2.x; c1 += f2.y;
        d0 += f3.x; d1 += f3.y;
    }
    for (; j < d; j++) {
        int s = g_csr[start + j];
        uint32_t u = __ldg(yp + (size_t)s * 32 + lane);
        float2 f = __half22float2(*(__half2*)&u);
        a0 += f.x; a1 += f.y;
    }
    float inv = g_inv[node];
    float2 r;
    r.x = fmaxf((a0 + b0 + c0 + d0) * inv, 0.f);
    r.y = fmaxf((a1 + b1 + c1 + d1) * inv, 0.f);
    ((float2*)hout)[(size_t)node * 32 + lane] = r;
}

extern "C" void kernel_launch(void* const* d_in, const int* in_sizes, int n_in,
                              void* d_out, int out_size) {
    const float* x = (const float*)d_in[0];
    const int* ei = (const int*)d_in[1];
    const float* W1 = (const float*)d_in[2];
    const float* W2 = (const float*)d_in[3];
    const float* W3 = (const float*)d_in[4];
    float* out = (float*)d_out;

    const int* src = ei;
    const int* dst = ei + E;

    const int ngrid = (N + 255) / 256;
    const int egrid = (E + 255) / 256;
    const int agrid = (N * 32 + 255) / 256;
    const int ggrid = (N + 127) / 128;   // 391

    float* h;  cudaGetSymbolAddress((void**)&h, g_h);
    __half* yh; cudaGetSymbolAddress((void**)&yh, g_yh);
    __nv_bfloat16* whi; cudaGetSymbolAddress((void**)&whi, g_Whi);
    __nv_bfloat16* wlo; cudaGetSymbolAddress((void**)&wlo, g_Wlo);

    const int SMEM128 = 2 * A_TILE + 2 * (128 * PITCH * 2);  // 139264
    const int SMEM64  = 2 * A_TILE + 2 * (64 * PITCH * 2);   // 104448
    cudaFuncSetAttribute(mma_gemm_kernel<128>, cudaFuncAttributeMaxDynamicSharedMemorySize, SMEM128);
    cudaFuncSetAttribute(mma_gemm_kernel<64>,  cudaFuncAttributeMaxDynamicSharedMemorySize, SMEM64);

    // CSR build
    zero_deg_kernel<<<ngrid, 256>>>();
    deg_kernel<<<egrid, 256>>>(dst);
    scan_block_kernel<<<NBLK, SCAN_BLK>>>();
    scan_sums_kernel<<<1, 32>>>();
    scan_add_kernel<<<ngrid, 256>>>();
    fill_csr_kernel<<<egrid, 256>>>(src, dst);

    // weight splits (single launch)
    wsplit_kernel<<<(40960 + 255) / 256, 256>>>(W1, W2, W3);

    // Layer 1
    mma_gemm_kernel<128><<<ggrid, 256, SMEM128>>>(x, whi, wlo, yh);
    agg128_kernel<<<agrid, 256>>>(h);

    // Layer 2
    mma_gemm_kernel<128><<<ggrid, 256, SMEM128>>>(h, whi + 16384, wlo + 16384, yh);
    agg128_kernel<<<agrid, 256>>>(h);

    // Layer 3 (64-dim)
    mma_gemm_kernel<64><<<ggrid, 256, SMEM64>>>(h, whi + 32768, wlo + 32768, yh);
    agg64_kernel<<<agrid, 256>>>(out);
}

// round 6
// speedup vs baseline: 2.7215x; 1.1651x over previous
#include <cuda_runtime.h>
#include <cuda_fp16.h>
#include <cstdint>

constexpr int N = 50000;     // nodes
constexpr int E = 800000;    // edges
constexpr int K = 128;       // feature dim

constexpr int SCAN_BLK = 1024;
constexpr int NBLK = (N + SCAN_BLK - 1) / SCAN_BLK;   // 49

// ---------------- device scratch ----------------
__device__ __align__(16) __half g_yh[(size_t)N * K];   // GEMM output (fp16)
__device__ __align__(16) __half g_h16[(size_t)N * K];  // activations (fp16)
__device__ float g_inv[N];
__device__ int   g_deg[N];
__device__ int   g_rp[N];
__device__ int   g_pos[N];
__device__ int   g_csr[E];
__device__ int   g_bsum[NBLK];
// W split: hi fp16, lo*1024 fp16.  W1(16384) W2(16384) W3(8192)
__device__ __align__(16) __half g_Whi[40960];
__device__ __align__(16) __half g_Wlo[40960];

// ---------------- helpers ----------------
__device__ __forceinline__ uint32_t smem_u32(const void* p) {
    uint32_t a;
    asm("{ .reg .u64 t; cvta.to.shared.u64 t, %1; cvt.u32.u64 %0, t; }" : "=r"(a) : "l"(p));
    return a;
}

#define LDMX4(r0, r1, r2, r3, addr)                                            \
    asm volatile("ldmatrix.sync.aligned.m8n8.x4.shared.b16 {%0,%1,%2,%3}, [%4];" \
                 : "=r"(r0), "=r"(r1), "=r"(r2), "=r"(r3) : "r"(addr))

#define MMAF16(d, a, b)                                                         \
    asm volatile("mma.sync.aligned.m16n8k16.row.col.f32.f16.f16.f32 "            \
                 "{%0,%1,%2,%3}, {%4,%5,%6,%7}, {%8,%9}, {%0,%1,%2,%3};"         \
                 : "+f"((d)[0]), "+f"((d)[1]), "+f"((d)[2]), "+f"((d)[3])        \
                 : "r"((a)[0]), "r"((a)[1]), "r"((a)[2]), "r"((a)[3]),           \
                   "r"((b)[0]), "r"((b)[1]))

// ---------------- fused: W split + deg zero ----------------
__global__ void wsplit_zero_kernel(const float* __restrict__ W1,
                                   const float* __restrict__ W2,
                                   const float* __restrict__ W3) {
    int i = blockIdx.x * blockDim.x + threadIdx.x;
    if (i < N) g_deg[i] = 0;
    if (i < 40960) {
        float v;
        if (i < 16384) v = W1[i];
        else if (i < 32768) v = W2[i - 16384];
        else v = W3[i - 32768];
        __half hi = __float2half_rn(v);
        __half lo = __float2half_rn((v - __half2float(hi)) * 1024.0f);
        g_Whi[i] = hi;
        g_Wlo[i] = lo;
    }
}

__global__ void deg_kernel(const int* __restrict__ dst) {
    int e = blockIdx.x * blockDim.x + threadIdx.x;
    if (e < E) atomicAdd(&g_deg[dst[e]], 1);
}

// shfl-based block scan (inclusive within block), writes exclusive rp + block sums
__global__ void scan_block_kernel() {
    __shared__ int wsum[32];
    int tid = threadIdx.x;
    int lane = tid & 31;
    int wid = tid >> 5;
    int i = blockIdx.x * SCAN_BLK + tid;
    int v = (i < N) ? g_deg[i] : 0;
    int s = v;
#pragma unroll
    for (int o = 1; o < 32; o <<= 1) {
        int t = __shfl_up_sync(0xFFFFFFFF, s, o);
        if (lane >= o) s += t;
    }
    if (lane == 31) wsum[wid] = s;
    __syncthreads();
    if (wid == 0) {
        int w = wsum[lane];
        int ws = w;
#pragma unroll
        for (int o = 1; o < 32; o <<= 1) {
            int t = __shfl_up_sync(0xFFFFFFFF, ws, o);
            if (lane >= o) ws += t;
        }
        wsum[lane] = ws - w;   // exclusive warp offsets
        if (lane == 31) g_bsum[blockIdx.x] = ws;   // block total
    }
    __syncthreads();
    if (i < N) g_rp[i] = s - v + wsum[wid];
}

// adds cross-block offsets (inline prefix over 49 bsums), computes pos & inv
__global__ void scan_add_kernel() {
    int i = blockIdx.x * blockDim.x + threadIdx.x;
    if (i < N) {
        int nb = i >> 10;
        int base = 0;
        for (int b = 0; b < nb; b++) base += g_bsum[b];
        int rp = g_rp[i] + base;
        g_rp[i] = rp;
        g_pos[i] = rp;
        g_inv[i] = 1.0f / (float)(g_deg[i] + 1);
    }
}

__global__ void fill_csr_kernel(const int* __restrict__ src, const int* __restrict__ dst) {
    int e = blockIdx.x * blockDim.x + threadIdx.x;
    if (e < E) {
        int slot = atomicAdd(&g_pos[dst[e]], 1);
        g_csr[slot] = src[e];
    }
}

// ---------------- HMMA GEMM: Yh = fp16( H @ W^T ) ----------------
// A fp16 (converted from fp32 for layer 1); W = hi + lo/1024 (two passes,
// second pass into a separate accumulator, recombined in epilogue).
constexpr int PITCH = 136;               // fp16 elems per smem row
constexpr int A_TILE = 128 * PITCH * 2;  // 34816 bytes

template <int DOUT, bool SRC32>
__global__ __launch_bounds__(256, 1)
void mma_gemm_kernel(const void* __restrict__ Hin,
                     const __half* __restrict__ Whi,
                     const __half* __restrict__ Wlo,
                     __half* __restrict__ Yh) {
    constexpr int B_TILE = DOUT * PITCH * 2;
    constexpr int OFF_A = 0;
    constexpr int OFF_BHI = A_TILE;
    constexpr int OFF_BLO = A_TILE + B_TILE;
    constexpr int NT = DOUT / 16;
    constexpr int NG = NT / 2;

    extern __shared__ char smem[];
    uint32_t sb = smem_u32(smem);
    int tid = threadIdx.x;
    int lane = tid & 31;
    int wid = tid >> 5;
    int wm = wid & 3;
    int wn = wid >> 2;
    int base = blockIdx.x * 128;

    // A prologue
    for (int p = tid; p < 128 * 64; p += 256) {
        int r = p >> 6;
        int c2 = p & 63;             // half2 index within row
        int node = base + r;
        uint32_t w = 0;
        if (node < N) {
            if (SRC32) {
                float2 v = *(const float2*)((const float*)Hin + (size_t)node * K + c2 * 2);
                __half2 h2 = __floats2half2_rn(v.x, v.y);
                w = *(uint32_t*)&h2;
            } else {
                w = ((const uint32_t*)Hin)[(size_t)node * 64 + c2];
            }
        }
        int byte = (r * PITCH + c2 * 2) * 2;
        *(uint32_t*)(smem + OFF_A + byte) = w;
    }
    // B prologue
    for (int p = tid; p < DOUT * 64; p += 256) {
        int r = p >> 6;
        int c2 = p & 63;
        int byte = (r * PITCH + c2 * 2) * 2;
        *(uint32_t*)(smem + OFF_BHI + byte) = ((const uint32_t*)Whi)[p];
        *(uint32_t*)(smem + OFF_BLO + byte) = ((const uint32_t*)Wlo)[p];
    }
    __syncthreads();

    int m = lane >> 3;
    int lr = lane & 7;
    int rb = wm * 32;
    int nb = wn * (DOUT / 2);

    uint32_t aoff0 = (uint32_t)(((rb + lr + (m & 1) * 8) * PITCH + (m >> 1) * 8) * 2);
    uint32_t aoff1 = aoff0 + 16 * PITCH * 2;
    uint32_t boff[NG];
#pragma unroll
    for (int g = 0; g < NG; g++)
        boff[g] = (uint32_t)(((nb + 16 * g + lr + (m >> 1) * 8) * PITCH + (m & 1) * 8) * 2);

    float acc[2][NT][4], accl[2][NT][4];
#pragma unroll
    for (int mt = 0; mt < 2; mt++)
#pragma unroll
        for (int nt = 0; nt < NT; nt++)
#pragma unroll
            for (int q = 0; q < 4; q++) { acc[mt][nt][q] = 0.f; accl[mt][nt][q] = 0.f; }

#pragma unroll
    for (int j = 0; j < 8; j++) {
        uint32_t kb = j * 32;
        uint32_t a[2][4], bhi[NT][2], blo[NT][2];
        LDMX4(a[0][0], a[0][1], a[0][2], a[0][3], sb + OFF_A + aoff0 + kb);
        LDMX4(a[1][0], a[1][1], a[1][2], a[1][3], sb + OFF_A + aoff1 + kb);
#pragma unroll
        for (int g = 0; g < NG; g++) {
            LDMX4(bhi[2 * g][0], bhi[2 * g][1], bhi[2 * g + 1][0], bhi[2 * g + 1][1],
                  sb + OFF_BHI + boff[g] + kb);
            LDMX4(blo[2 * g][0], blo[2 * g][1], blo[2 * g + 1][0], blo[2 * g + 1][1],
                  sb + OFF_BLO + boff[g] + kb);
        }
#pragma unroll
        for (int mt = 0; mt < 2; mt++)
#pragma unroll
            for (int nt = 0; nt < NT; nt++) {
                MMAF16(acc[mt][nt], a[mt], bhi[nt]);
                MMAF16(accl[mt][nt], a[mt], blo[nt]);
            }
    }

    // epilogue: recombine + fp16 store
    constexpr float INVS = 1.0f / 1024.0f;
    int r0 = base + rb + (lane >> 2);
#pragma unroll
    for (int mt = 0; mt < 2; mt++) {
        int row = r0 + 16 * mt;
#pragma unroll
        for (int nt = 0; nt < NT; nt++) {
            int col = nb + 8 * nt + 2 * (lane & 3);
            if (row < N) {
                float v0 = fmaf(accl[mt][nt][0], INVS, acc[mt][nt][0]);
                float v1 = fmaf(accl[mt][nt][1], INVS, acc[mt][nt][1]);
                __half2 h = __floats2half2_rn(v0, v1);
                *(__half2*)(Yh + (size_t)row * DOUT + col) = h;
            }
            if (row + 8 < N) {
                float v0 = fmaf(accl[mt][nt][2], INVS, acc[mt][nt][2]);
                float v1 = fmaf(accl[mt][nt][3], INVS, acc[mt][nt][3]);
                __half2 h = __floats2half2_rn(v0, v1);
                *(__half2*)(Yh + (size_t)(row + 8) * DOUT + col) = h;
            }
        }
    }
}

// ---------------- aggregation: h = relu(inv*(sum_nbr y + y_self)) ----------------
__device__ __forceinline__ void acc_h4(float& a0, float& a1, float& a2, float& a3, uint2 u) {
    float2 f0 = __half22float2(*(__half2*)&u.x);
    float2 f1 = __half22float2(*(__half2*)&u.y);
    a0 += f0.x; a1 += f0.y; a2 += f1.x; a3 += f1.y;
}

// 128-dim, warp/node, lane = 4 halves, unroll 8, writes fp16
__global__ void agg128_kernel(__half* __restrict__ hout) {
    int gid = blockIdx.x * blockDim.x + threadIdx.x;
    int node = gid >> 5;
    int lane = gid & 31;
    if (node >= N) return;
    const uint2* yp = (const uint2*)g_yh;
    int start = g_rp[node];
    int d = g_deg[node];

    float a0 = 0, a1 = 0, a2 = 0, a3 = 0;
    float b0 = 0, b1 = 0, b2 = 0, b3 = 0;
    float c0 = 0, c1 = 0, c2 = 0, c3 = 0;
    float e0 = 0, e1 = 0, e2 = 0, e3 = 0;

    acc_h4(a0, a1, a2, a3, __ldg(yp + (size_t)node * 32 + lane));

    int j = 0;
    for (; j + 8 <= d; j += 8) {
        const int* cs = g_csr + start + j;
        int s0 = cs[0], s1 = cs[1], s2 = cs[2], s3 = cs[3];
        int s4 = cs[4], s5 = cs[5], s6 = cs[6], s7 = cs[7];
        uint2 u0 = __ldg(yp + (size_t)s0 * 32 + lane);
        uint2 u1 = __ldg(yp + (size_t)s1 * 32 + lane);
        uint2 u2 = __ldg(yp + (size_t)s2 * 32 + lane);
        uint2 u3 = __ldg(yp + (size_t)s3 * 32 + lane);
        uint2 u4 = __ldg(yp + (size_t)s4 * 32 + lane);
        uint2 u5 = __ldg(yp + (size_t)s5 * 32 + lane);
        uint2 u6 = __ldg(yp + (size_t)s6 * 32 + lane);
        uint2 u7 = __ldg(yp + (size_t)s7 * 32 + lane);
        acc_h4(a0, a1, a2, a3, u0);
        acc_h4(b0, b1, b2, b3, u1);
        acc_h4(c0, c1, c2, c3, u2);
        acc_h4(e0, e1, e2, e3, u3);
        acc_h4(a0, a1, a2, a3, u4);
        acc_h4(b0, b1, b2, b3, u5);
        acc_h4(c0, c1, c2, c3, u6);
        acc_h4(e0, e1, e2, e3, u7);
    }
    for (; j + 4 <= d; j += 4) {
        const int* cs = g_csr + start + j;
        int s0 = cs[0], s1 = cs[1], s2 = cs[2], s3 = cs[3];
        uint2 u0 = __ldg(yp + (size_t)s0 * 32 + lane);
        uint2 u1 = __ldg(yp + (size_t)s1 * 32 + lane);
        uint2 u2 = __ldg(yp + (size_t)s2 * 32 + lane);
        uint2 u3 = __ldg(yp + (size_t)s3 * 32 + lane);
        acc_h4(a0, a1, a2, a3, u0);
        acc_h4(b0, b1, b2, b3, u1);
        acc_h4(c0, c1, c2, c3, u2);
        acc_h4(e0, e1, e2, e3, u3);
    }
    for (; j < d; j++) {
        int s = g_csr[start + j];
        acc_h4(a0, a1, a2, a3, __ldg(yp + (size_t)s * 32 + lane));
    }
    float inv = g_inv[node];
    float r0 = fmaxf((a0 + b0 + c0 + e0) * inv, 0.f);
    float r1 = fmaxf((a1 + b1 + c1 + e1) * inv, 0.f);
    float r2 = fmaxf((a2 + b2 + c2 + e2) * inv, 0.f);
    float r3 = fmaxf((a3 + b3 + c3 + e3) * inv, 0.f);
    __half2 p0 = __floats2half2_rn(r0, r1);
    __half2 p1 = __floats2half2_rn(r2, r3);
    uint2 w;
    w.x = *(uint32_t*)&p0;
    w.y = *(uint32_t*)&p1;
    ((uint2*)hout)[(size_t)node * 32 + lane] = w;
}

// 64-dim final layer, warp/node, lane = 2 halves, unroll 8, writes fp32 out
__global__ void agg64_kernel(float* __restrict__ hout) {
    int gid = blockIdx.x * blockDim.x + threadIdx.x;
    int node = gid >> 5;
    int lane = gid & 31;
    if (node >= N) return;
    const uint32_t* yp = (const uint32_t*)g_yh;
    int start = g_rp[node];
    int d = g_deg[node];

    float a0 = 0, a1 = 0, b0 = 0, b1 = 0, c0 = 0, c1 = 0, e0 = 0, e1 = 0;
    {
        uint32_t u = __ldg(yp + (size_t)node * 32 + lane);
        float2 f = __half22float2(*(__half2*)&u);
        a0 += f.x; a1 += f.y;
    }
    int j = 0;
    for (; j + 8 <= d; j += 8) {
        const int* cs = g_csr + start + j;
        int s0 = cs[0], s1 = cs[1], s2 = cs[2], s3 = cs[3];
        int s4 = cs[4], s5 = cs[5], s6 = cs[6], s7 = cs[7];
        uint32_t u0 = __ldg(yp + (size_t)s0 * 32 + lane);
        uint32_t u1 = __ldg(yp + (size_t)s1 * 32 + lane);
        uint32_t u2 = __ldg(yp + (size_t)s2 * 32 + lane);
        uint32_t u3 = __ldg(yp + (size_t)s3 * 32 + lane);
        uint32_t u4 = __ldg(yp + (size_t)s4 * 32 + lane);
        uint32_t u5 = __ldg(yp + (size_t)s5 * 32 + lane);
        uint32_t u6 = __ldg(yp + (size_t)s6 * 32 + lane);
        uint32_t u7 = __ldg(yp + (size_t)s7 * 32 + lane);
        float2 f0 = __half22float2(*(__half2*)&u0);
        float2 f1 = __half22float2(*(__half2*)&u1);
        float2 f2 = __half22float2(*(__half2*)&u2);
        float2 f3 = __half22float2(*(__half2*)&u3);
        float2 f4 = __half22float2(*(__half2*)&u4);
        float2 f5 = __half22float2(*(__half2*)&u5);
        float2 f6 = __half22float2(*(__half2*)&u6);
        float2 f7 = __half22float2(*(__half2*)&u7);
        a0 += f0.x; a1 += f0.y;  b0 += f1.x; b1 += f1.y;
        c0 += f2.x; c1 += f2.y;  e0 += f3.x; e1 += f3.y;
        a0 += f4.x; a1 += f4.y;  b0 += f5.x; b1 += f5.y;
        c0 += f6.x; c1 += f6.y;  e0 += f7.x; e1 += f7.y;
    }
    for (; j + 4 <= d; j += 4) {
        const int* cs = g_csr + start + j;
        int s0 = cs[0], s1 = cs[1], s2 = cs[2], s3 = cs[3];
        uint32_t u0 = __ldg(yp + (size_t)s0 * 32 + lane);
        uint32_t u1 = __ldg(yp + (size_t)s1 * 32 + lane);
        uint32_t u2 = __ldg(yp + (size_t)s2 * 32 + lane);
        uint32_t u3 = __ldg(yp + (size_t)s3 * 32 + lane);
        float2 f0 = __half22float2(*(__half2*)&u0);
        float2 f1 = __half22float2(*(__half2*)&u1);
        float2 f2 = __half22float2(*(__half2*)&u2);
        float2 f3 = __half22float2(*(__half2*)&u3);
        a0 += f0.x; a1 += f0.y;  b0 += f1.x; b1 += f1.y;
        c0 += f2.x; c1 += f2.y;  e0 += f3.x; e1 += f3.y;
    }
    for (; j < d; j++) {
        int s = g_csr[start + j];
        uint32_t u = __ldg(yp + (size_t)s * 32 + lane);
        float2 f = __half22float2(*(__half2*)&u);
        a0 += f.x; a1 += f.y;
    }
    float inv = g_inv[node];
    float2 r;
    r.x = fmaxf((a0 + b0 + c0 + e0) * inv, 0.f);
    r.y = fmaxf((a1 + b1 + c1 + e1) * inv, 0.f);
    ((float2*)hout)[(size_t)node * 32 + lane] = r;
}

extern "C" void kernel_launch(void* const* d_in, const int* in_sizes, int n_in,
                              void* d_out, int out_size) {
    const float* x = (const float*)d_in[0];
    const int* ei = (const int*)d_in[1];
    const float* W1 = (const float*)d_in[2];
    const float* W2 = (const float*)d_in[3];
    const float* W3 = (const float*)d_in[4];
    float* out = (float*)d_out;

    const int* src = ei;
    const int* dst = ei + E;

    const int ngrid = (N + 255) / 256;
    const int egrid = (E + 255) / 256;
    const int agrid = (N * 32 + 255) / 256;
    const int ggrid = (N + 127) / 128;   // 391

    __half* h16; cudaGetSymbolAddress((void**)&h16, g_h16);
    __half* yh;  cudaGetSymbolAddress((void**)&yh, g_yh);
    __half* whi; cudaGetSymbolAddress((void**)&whi, g_Whi);
    __half* wlo; cudaGetSymbolAddress((void**)&wlo, g_Wlo);

    const int SMEM128 = A_TILE + 2 * (128 * PITCH * 2);  // 104448
    const int SMEM64  = A_TILE + 2 * (64 * PITCH * 2);   // 69632
    cudaFuncSetAttribute((const void*)mma_gemm_kernel<128, true>,
                         cudaFuncAttributeMaxDynamicSharedMemorySize, SMEM128);
    cudaFuncSetAttribute((const void*)mma_gemm_kernel<128, false>,
                         cudaFuncAttributeMaxDynamicSharedMemorySize, SMEM128);
    cudaFuncSetAttribute((const void*)mma_gemm_kernel<64, false>,
                         cudaFuncAttributeMaxDynamicSharedMemorySize, SMEM64);

    // CSR build + weight split
    wsplit_zero_kernel<<<ngrid, 256>>>(W1, W2, W3);
    deg_kernel<<<egrid, 256>>>(dst);
    scan_block_kernel<<<NBLK, SCAN_BLK>>>();
    scan_add_kernel<<<ngrid, 256>>>();
    fill_csr_kernel<<<egrid, 256>>>(src, dst);

    // Layer 1
    mma_gemm_kernel<128, true><<<ggrid, 256, SMEM128>>>(x, whi, wlo, yh);
    agg128_kernel<<<agrid, 256>>>(h16);

    // Layer 2
    mma_gemm_kernel<128, false><<<ggrid, 256, SMEM128>>>(h16, whi + 16384, wlo + 16384, yh);
    agg128_kernel<<<agrid, 256>>>(h16);

    // Layer 3 (64-dim)
    mma_gemm_kernel<64, false><<<ggrid, 256, SMEM64>>>(h16, whi + 32768, wlo + 32768, yh);
    agg64_kernel<<<agrid, 256>>>(out);
}